// round 1
// baseline (speedup 1.0000x reference)
#include <cuda_runtime.h>
#include <math.h>

#define LAYERS 2
#define BB 8
#define TT 512
#define HH 128
#define MM (BB*TT)   // 4096 rows

// ---------------- device scratch (no allocations allowed) ----------------
__device__ float g_Wt[LAYERS][6][HH*HH];   // transposed weights: [l][p][d][h]
__device__ float g_proj[6][MM*HH];         // q,k,v,i,f,o activations (post-nonlinearity)
__device__ float g_h[MM*HH];               // inter-layer hidden state

// ---------------- weight transpose: W[l][h][d] -> Wt[l][p][d][h] ----------------
__global__ void transpose_w_kernel(const float* __restrict__ Wq, const float* __restrict__ Wk,
                                   const float* __restrict__ Wv, const float* __restrict__ Wi,
                                   const float* __restrict__ Wf, const float* __restrict__ Wo)
{
    int idx = blockIdx.x * blockDim.x + threadIdx.x;
    const int total = LAYERS * 6 * HH * HH;
    if (idx >= total) return;
    int l   = idx / (6 * HH * HH);
    int rem = idx - l * 6 * HH * HH;
    int p   = rem / (HH * HH);
    int e   = rem - p * (HH * HH);
    int d   = e >> 7;
    int h   = e & 127;
    const float* W = (p == 0) ? Wq : (p == 1) ? Wk : (p == 2) ? Wv
                   : (p == 3) ? Wi : (p == 4) ? Wf : Wo;
    g_Wt[l][p][d * HH + h] = W[l * HH * HH + h * HH + d];
}

// ---------------- fused projection GEMM + bias + activation ----------------
// out[p][m][h] = act_p( sum_d X[m][d] * W_p[h][d] + b_p[h] )
// grid = (MM/128, 6), block = 256, 128x128 tile, 8x8 microtile, BK=8.
__global__ __launch_bounds__(256) void proj_gemm_kernel(
    const float* __restrict__ X, int layer,
    const float* __restrict__ bq, const float* __restrict__ bk,
    const float* __restrict__ bv, const float* __restrict__ bi,
    const float* __restrict__ bf, const float* __restrict__ bo)
{
    const float* __restrict__ Xp = X ? X : g_h;
    const int p  = blockIdx.y;
    const int m0 = blockIdx.x * 128;
    const float* __restrict__ Wt = g_Wt[layer][p];

    __shared__ float As[8][128];
    __shared__ float Bs[8][128];

    float acc[8][8];
    #pragma unroll
    for (int i = 0; i < 8; i++)
        #pragma unroll
        for (int j = 0; j < 8; j++) acc[i][j] = 0.0f;

    const int tid = threadIdx.x;
    const int tx = tid & 15;          // 16 col groups
    const int ty = tid >> 4;          // 16 row groups
    const int lm = tid >> 1;          // 0..127 : M row for X load
    const int lk = (tid & 1) << 2;    // 0 or 4 : K offset for X load
    const int wh = (tid & 31) << 2;   // 0..124 : H offset for W load
    const int wk = tid >> 5;          // 0..7   : K row for W load

    for (int k0 = 0; k0 < HH; k0 += 8) {
        float4 xa = *(const float4*)(Xp + (m0 + lm) * HH + k0 + lk);
        As[lk + 0][lm] = xa.x;
        As[lk + 1][lm] = xa.y;
        As[lk + 2][lm] = xa.z;
        As[lk + 3][lm] = xa.w;
        *(float4*)(&Bs[wk][wh]) = *(const float4*)(Wt + (k0 + wk) * HH + wh);
        __syncthreads();
        #pragma unroll
        for (int kk = 0; kk < 8; kk++) {
            float a[8], b[8];
            *(float4*)(a)     = *(const float4*)(&As[kk][ty * 8]);
            *(float4*)(a + 4) = *(const float4*)(&As[kk][ty * 8 + 4]);
            *(float4*)(b)     = *(const float4*)(&Bs[kk][tx * 8]);
            *(float4*)(b + 4) = *(const float4*)(&Bs[kk][tx * 8 + 4]);
            #pragma unroll
            for (int i = 0; i < 8; i++)
                #pragma unroll
                for (int j = 0; j < 8; j++)
                    acc[i][j] = fmaf(a[i], b[j], acc[i][j]);
        }
        __syncthreads();
    }

    const float* __restrict__ bias =
        (p == 0) ? bq : (p == 1) ? bk : (p == 2) ? bv
      : (p == 3) ? bi : (p == 4) ? bf : bo;
    float* __restrict__ out = g_proj[p];
    const float kscale = 0.088388347648318447f;  // 1/sqrt(128)

    #pragma unroll
    for (int i = 0; i < 8; i++) {
        const int m = m0 + ty * 8 + i;
        #pragma unroll
        for (int j = 0; j < 8; j++) {
            const int h = tx * 8 + j;
            float v = acc[i][j] + bias[layer * HH + h];
            if (p == 1)      v *= kscale;               // k / sqrt(H)
            else if (p == 3) v = expf(v);               // input gate
            else if (p >= 4) v = 1.0f / (1.0f + expf(-v)); // f, o sigmoid
            out[m * HH + h] = v;
        }
    }
}

// ---------------- sequential mLSTM scan, row-parallel across CTAs ----------------
// grid = (16 row-slices, 8 batches), block = 128.
// Each CTA owns 8 rows of C (16 lanes/row, 8 C columns per thread in registers).
// Every CTA keeps a full redundant copy of n (thread tid owns n[tid]) so denom
// is computed locally with zero cross-CTA traffic.
__global__ __launch_bounds__(128) void scan_kernel(float* __restrict__ outh)
{
    float* __restrict__ dst = outh ? outh : g_h;
    const int b   = blockIdx.y;
    const int tid = threadIdx.x;
    const int cg  = tid & 15;                 // column group
    const int r   = (blockIdx.x << 3) + (tid >> 4);  // global row 0..127
    const int c8  = cg << 3;                  // first of 8 C columns

    __shared__ float sq[2][HH], sk[2][HH], sv[2][HH];
    __shared__ float si[2][HH], sf[2][HH], so[2][HH];
    __shared__ float sden[2][4];

    float C[8];
    #pragma unroll
    for (int j = 0; j < 8; j++) C[j] = 0.0f;
    float n_l = 0.0f;

    const float* __restrict__ Pq = g_proj[0] + b * TT * HH;
    const float* __restrict__ Pk = g_proj[1] + b * TT * HH;
    const float* __restrict__ Pv = g_proj[2] + b * TT * HH;
    const float* __restrict__ Pi = g_proj[3] + b * TT * HH;
    const float* __restrict__ Pf = g_proj[4] + b * TT * HH;
    const float* __restrict__ Po = g_proj[5] + b * TT * HH;

    // prefetch t = 0
    float pq = Pq[tid], pk = Pk[tid], pv = Pv[tid];
    float pi = Pi[tid], pf = Pf[tid], po = Po[tid];

    for (int t = 0; t < TT; t++) {
        const int buf = t & 1;
        sq[buf][tid] = pq; sk[buf][tid] = pk; sv[buf][tid] = pv;
        si[buf][tid] = pi; sf[buf][tid] = pf; so[buf][tid] = po;

        // denom partial with OLD n, then update n
        float pd = n_l * pq;
        n_l = fmaf(pf, n_l, pi * pk);

        // prefetch next step while reductions run
        if (t + 1 < TT) {
            const int off = (t + 1) * HH + tid;
            pq = Pq[off]; pk = Pk[off]; pv = Pv[off];
            pi = Pi[off]; pf = Pf[off]; po = Po[off];
        }

        #pragma unroll
        for (int o = 16; o > 0; o >>= 1)
            pd += __shfl_xor_sync(0xffffffffu, pd, o);
        if ((tid & 31) == 0) sden[buf][tid >> 5] = pd;
        __syncthreads();

        float denom = sden[buf][0] + sden[buf][1] + sden[buf][2] + sden[buf][3];
        denom = fmaxf(fabsf(denom), 1.0f);

        float4 qa = *(const float4*)(&sq[buf][c8]);
        float4 qb = *(const float4*)(&sq[buf][c8 + 4]);
        float4 ka = *(const float4*)(&sk[buf][c8]);
        float4 kb = *(const float4*)(&sk[buf][c8 + 4]);
        float fr = sf[buf][r], ir = si[buf][r];
        float vr = sv[buf][r], orr = so[buf][r];

        float dot = C[0]*qa.x + C[1]*qa.y + C[2]*qa.z + C[3]*qa.w
                  + C[4]*qb.x + C[5]*qb.y + C[6]*qb.z + C[7]*qb.w;
        #pragma unroll
        for (int o = 8; o > 0; o >>= 1)
            dot += __shfl_xor_sync(0xffffffffu, dot, o);

        if (cg == 0) dst[(b * TT + t) * HH + r] = orr * dot / denom;

        const float aa = ir * vr;
        C[0] = fmaf(fr, C[0], aa * ka.x);
        C[1] = fmaf(fr, C[1], aa * ka.y);
        C[2] = fmaf(fr, C[2], aa * ka.z);
        C[3] = fmaf(fr, C[3], aa * ka.w);
        C[4] = fmaf(fr, C[4], aa * kb.x);
        C[5] = fmaf(fr, C[5], aa * kb.y);
        C[6] = fmaf(fr, C[6], aa * kb.z);
        C[7] = fmaf(fr, C[7], aa * kb.w);
    }
}

// ---------------- launcher ----------------
extern "C" void kernel_launch(void* const* d_in, const int* in_sizes, int n_in,
                              void* d_out, int out_size)
{
    const float* x  = (const float*)d_in[0];
    const float* Wq = (const float*)d_in[1];
    const float* Wk = (const float*)d_in[2];
    const float* Wv = (const float*)d_in[3];
    const float* Wi = (const float*)d_in[4];
    const float* Wf = (const float*)d_in[5];
    const float* Wo = (const float*)d_in[6];
    const float* bq = (const float*)d_in[7];
    const float* bk = (const float*)d_in[8];
    const float* bv = (const float*)d_in[9];
    const float* bi = (const float*)d_in[10];
    const float* bf = (const float*)d_in[11];
    const float* bo = (const float*)d_in[12];
    float* out = (float*)d_out;

    const int total_w = LAYERS * 6 * HH * HH;
    transpose_w_kernel<<<(total_w + 255) / 256, 256>>>(Wq, Wk, Wv, Wi, Wf, Wo);

    dim3 ggrid(MM / 128, 6);
    dim3 sgrid(16, BB);

    // layer 0
    proj_gemm_kernel<<<ggrid, 256>>>(x, 0, bq, bk, bv, bi, bf, bo);
    scan_kernel<<<sgrid, 128>>>(nullptr);      // writes g_h
    // layer 1
    proj_gemm_kernel<<<ggrid, 256>>>(nullptr, 1, bq, bk, bv, bi, bf, bo);
    scan_kernel<<<sgrid, 128>>>(out);          // writes final output
}